// round 1
// baseline (speedup 1.0000x reference)
#include <cuda_runtime.h>

#define E_EXP   8
#define DIN     2
#define DOUT    3
#define H_DIM   256
#define NHID    3
#define OMEGA   30.0f
#define NPTS    65536

#define TILE_M  64
#define NTHR    256
#define KK      16
#define NCHUNK  (H_DIM / KK)   // 16
#define HSTR    260            // padded row stride (floats) for hA

// ---- shared memory layout (floats) ----
#define OFF_HA    0
#define OFF_WS    (OFF_HA + TILE_M * HSTR)          // 16640
#define OFF_XS    (OFF_WS + 2 * KK * H_DIM)         // +8192 = 24832
#define OFF_GSM   (OFF_XS + TILE_M * 2)             // +128  = 24960
#define OFF_WOUT  (OFF_GSM + TILE_M * E_EXP)        // +512  = 25472
#define OFF_RED   (OFF_WOUT + H_DIM * 4)            // +1024 = 26496
#define OFF_COMB  (OFF_RED + 4 * TILE_M * DOUT)     // +768  = 27264
#define SMEM_FLOATS (OFF_COMB + TILE_M * DOUT)      // 27456
#define SMEM_BYTES  (SMEM_FLOATS * 4)               // 109824

typedef unsigned long long u64;

static __device__ __forceinline__ u64 fma2(u64 a, u64 b, u64 c) {
    u64 d;
    asm("fma.rn.f32x2 %0, %1, %2, %3;" : "=l"(d) : "l"(a), "l"(b), "l"(c));
    return d;
}
static __device__ __forceinline__ u64 pk2(float lo, float hi) {
    u64 r;
    asm("mov.b64 %0, {%1, %2};" : "=l"(r) : "f"(lo), "f"(hi));
    return r;
}
static __device__ __forceinline__ float2 upk2(u64 v) {
    float2 f;
    asm("mov.b64 {%0, %1}, %2;" : "=f"(f.x), "=f"(f.y) : "l"(v));
    return f;
}

// Fast accurate sinf for |x| <~ 1000: 2-step Cody-Waite reduction by pi/2,
// pi/4 minimax polys, quadrant select. All FFMA — avoids the MUFU.SIN
// throughput wall (rt_SMSP=8) entirely.
static __device__ __forceinline__ float fast_sin(float a) {
    float j = rintf(a * 0.63661977236758134308f);   // 2/pi
    int q = (int)j;
    float r = fmaf(j, -1.57079637050628662109375f, a);   // hi = 0x3FC90FDB
    r = fmaf(j, 4.37113883e-8f, r);                      // hi - pi/2 correction
    float z = r * r;
    // sin poly on [-pi/4, pi/4]
    float sp = fmaf(z, -1.95152959e-4f, 8.33216087e-3f);
    sp = fmaf(z, sp, -1.66666546e-1f);
    sp = fmaf(sp * z, r, r);
    // cos poly on [-pi/4, pi/4]
    float cp = fmaf(z, 2.44331571e-5f, -1.38873163e-3f);
    cp = fmaf(z, cp, 4.16666418e-2f);
    cp = fmaf(z, cp, -5.0e-1f);
    cp = fmaf(z, cp, 1.0f);
    float res = (q & 1) ? cp : sp;
    return (q & 2) ? -res : res;
}

extern __shared__ float smem_raw[];

__global__ void __launch_bounds__(NTHR, 2)
moe_siren_kernel(const float* __restrict__ x,
                 const float* __restrict__ gate_W,
                 const float* __restrict__ gate_b,
                 const float* __restrict__ W0,
                 const float* __restrict__ b0,
                 const float* __restrict__ Wh,
                 const float* __restrict__ bh,
                 const float* __restrict__ Wout,
                 const float* __restrict__ bout,
                 float* __restrict__ out)
{
    float* hA     = smem_raw + OFF_HA;
    float* Ws     = smem_raw + OFF_WS;
    float* xs     = smem_raw + OFF_XS;
    float* gsm    = smem_raw + OFF_GSM;
    float* wout_s = smem_raw + OFF_WOUT;
    float* red    = smem_raw + OFF_RED;
    float* comb   = smem_raw + OFF_COMB;

    const int tid = threadIdx.x;
    const int tc  = tid & 31;      // 0..31 -> cols 4*tc and 128+4*tc
    const int tr  = tid >> 5;      // 0..7  -> rows tr*8 .. tr*8+7
    const int n0  = blockIdx.x * TILE_M;

    // ---- load x tile ----
    if (tid < TILE_M * 2) xs[tid] = x[n0 * 2 + tid];
    __syncthreads();

    // ---- gate softmax + combine init (one thread per row) ----
    if (tid < TILE_M) {
        float x0 = xs[tid * 2 + 0], x1 = xs[tid * 2 + 1];
        float lg[E_EXP];
        float mx = -1e30f;
        #pragma unroll
        for (int e = 0; e < E_EXP; e++) {
            float v = fmaf(x0, gate_W[e], fmaf(x1, gate_W[E_EXP + e], gate_b[e]));
            lg[e] = v; mx = fmaxf(mx, v);
        }
        float s = 0.0f;
        #pragma unroll
        for (int e = 0; e < E_EXP; e++) { lg[e] = expf(lg[e] - mx); s += lg[e]; }
        float inv = 1.0f / s;
        #pragma unroll
        for (int e = 0; e < E_EXP; e++) gsm[tid * E_EXP + e] = lg[e] * inv;
        comb[tid * 3 + 0] = 0.0f; comb[tid * 3 + 1] = 0.0f; comb[tid * 3 + 2] = 0.0f;
    }

    for (int e = 0; e < E_EXP; e++) {
        // ================= layer 0 (K=2) =================
        const float* W0e = W0 + e * 2 * H_DIM;
        const float* b0e = b0 + e * H_DIM;
        float4 w0A = *(const float4*)(W0e + 4 * tc);
        float4 w0B = *(const float4*)(W0e + 128 + 4 * tc);
        float4 w1A = *(const float4*)(W0e + H_DIM + 4 * tc);
        float4 w1B = *(const float4*)(W0e + H_DIM + 128 + 4 * tc);
        float4 bA  = *(const float4*)(b0e + 4 * tc);
        float4 bB  = *(const float4*)(b0e + 128 + 4 * tc);
        __syncthreads();   // prior out-phase reads of hA done; gsm/comb ready
        #pragma unroll
        for (int i = 0; i < 8; i++) {
            int r = tr * 8 + i;
            float x0 = xs[r * 2 + 0], x1 = xs[r * 2 + 1];
            float4 oA, oB;
            oA.x = fast_sin(OMEGA * fmaf(x0, w0A.x, fmaf(x1, w1A.x, bA.x)));
            oA.y = fast_sin(OMEGA * fmaf(x0, w0A.y, fmaf(x1, w1A.y, bA.y)));
            oA.z = fast_sin(OMEGA * fmaf(x0, w0A.z, fmaf(x1, w1A.z, bA.z)));
            oA.w = fast_sin(OMEGA * fmaf(x0, w0A.w, fmaf(x1, w1A.w, bA.w)));
            oB.x = fast_sin(OMEGA * fmaf(x0, w0B.x, fmaf(x1, w1B.x, bB.x)));
            oB.y = fast_sin(OMEGA * fmaf(x0, w0B.y, fmaf(x1, w1B.y, bB.y)));
            oB.z = fast_sin(OMEGA * fmaf(x0, w0B.z, fmaf(x1, w1B.z, bB.z)));
            oB.w = fast_sin(OMEGA * fmaf(x0, w0B.w, fmaf(x1, w1B.w, bB.w)));
            *(float4*)&hA[r * HSTR + 4 * tc]       = oA;
            *(float4*)&hA[r * HSTR + 128 + 4 * tc] = oB;
        }
        __syncthreads();

        // ================= hidden layers (256x256 GEMM + sin) =================
        for (int l = 0; l < NHID; l++) {
            const float* W  = Wh + ((size_t)(e * NHID + l)) * H_DIM * H_DIM;
            const float* bb = bh + (e * NHID + l) * H_DIM;

            u64 acc[8][4];
            #pragma unroll
            for (int i = 0; i < 8; i++)
                #pragma unroll
                for (int jj = 0; jj < 4; jj++) acc[i][jj] = 0ull;

            // preload chunk 0 into Ws[0]
            float4 ld[4];
            #pragma unroll
            for (int t = 0; t < 4; t++)
                ld[t] = *(const float4*)(W + (tid + t * 256) * 4);
            #pragma unroll
            for (int t = 0; t < 4; t++)
                *(float4*)(Ws + (tid + t * 256) * 4) = ld[t];
            __syncthreads();

            for (int kc = 0; kc < NCHUNK; kc++) {
                int cur = kc & 1;
                if (kc + 1 < NCHUNK) {
                    const float* src = W + (kc + 1) * KK * H_DIM;
                    #pragma unroll
                    for (int t = 0; t < 4; t++)
                        ld[t] = *(const float4*)(src + (tid + t * 256) * 4);
                }
                const float* Wc = Ws + cur * KK * H_DIM;
                #pragma unroll
                for (int kk = 0; kk < KK; kk++) {
                    float4 wA = *(const float4*)(Wc + kk * H_DIM + 4 * tc);
                    float4 wB = *(const float4*)(Wc + kk * H_DIM + 128 + 4 * tc);
                    u64 w0p = pk2(wA.x, wA.y), w1p = pk2(wA.z, wA.w);
                    u64 w2p = pk2(wB.x, wB.y), w3p = pk2(wB.z, wB.w);
                    int k = kc * KK + kk;
                    #pragma unroll
                    for (int i = 0; i < 8; i++) {
                        float a = hA[(tr * 8 + i) * HSTR + k];
                        u64 a2 = pk2(a, a);
                        acc[i][0] = fma2(a2, w0p, acc[i][0]);
                        acc[i][1] = fma2(a2, w1p, acc[i][1]);
                        acc[i][2] = fma2(a2, w2p, acc[i][2]);
                        acc[i][3] = fma2(a2, w3p, acc[i][3]);
                    }
                }
                if (kc + 1 < NCHUNK) {
                    float* Wn = Ws + (cur ^ 1) * KK * H_DIM;
                    #pragma unroll
                    for (int t = 0; t < 4; t++)
                        *(float4*)(Wn + (tid + t * 256) * 4) = ld[t];
                }
                __syncthreads();
            }

            // epilogue: bias + sin, write back in place (all reads of hA done)
            float4 bA4 = *(const float4*)(bb + 4 * tc);
            float4 bB4 = *(const float4*)(bb + 128 + 4 * tc);
            #pragma unroll
            for (int i = 0; i < 8; i++) {
                int r = tr * 8 + i;
                float2 v0 = upk2(acc[i][0]);
                float2 v1 = upk2(acc[i][1]);
                float2 v2 = upk2(acc[i][2]);
                float2 v3 = upk2(acc[i][3]);
                float4 oA, oB;
                oA.x = fast_sin(OMEGA * (v0.x + bA4.x));
                oA.y = fast_sin(OMEGA * (v0.y + bA4.y));
                oA.z = fast_sin(OMEGA * (v1.x + bA4.z));
                oA.w = fast_sin(OMEGA * (v1.y + bA4.w));
                oB.x = fast_sin(OMEGA * (v2.x + bB4.x));
                oB.y = fast_sin(OMEGA * (v2.y + bB4.y));
                oB.z = fast_sin(OMEGA * (v3.x + bB4.z));
                oB.w = fast_sin(OMEGA * (v3.y + bB4.w));
                *(float4*)&hA[r * HSTR + 4 * tc]       = oA;
                *(float4*)&hA[r * HSTR + 128 + 4 * tc] = oB;
            }
            __syncthreads();
        }

        // ================= output layer (H -> 3) + gated combine =================
        {   // stage Wout[e] (256x3) into padded smem [256][4]
            const float* We = Wout + e * H_DIM * 3;
            wout_s[tid * 4 + 0] = We[tid * 3 + 0];
            wout_s[tid * 4 + 1] = We[tid * 3 + 1];
            wout_s[tid * 4 + 2] = We[tid * 3 + 2];
            wout_s[tid * 4 + 3] = 0.0f;
        }
        __syncthreads();
        {
            int r = tid & 63;
            int p = tid >> 6;       // 4 partial sums per row
            float s0 = 0.0f, s1 = 0.0f, s2 = 0.0f;
            #pragma unroll
            for (int kk = 0; kk < 16; kk++) {
                int kb = p * 64 + kk * 4;
                float4 h4 = *(const float4*)&hA[r * HSTR + kb];
                s0 = fmaf(h4.x, wout_s[(kb + 0) * 4 + 0], s0);
                s1 = fmaf(h4.x, wout_s[(kb + 0) * 4 + 1], s1);
                s2 = fmaf(h4.x, wout_s[(kb + 0) * 4 + 2], s2);
                s0 = fmaf(h4.y, wout_s[(kb + 1) * 4 + 0], s0);
                s1 = fmaf(h4.y, wout_s[(kb + 1) * 4 + 1], s1);
                s2 = fmaf(h4.y, wout_s[(kb + 1) * 4 + 2], s2);
                s0 = fmaf(h4.z, wout_s[(kb + 2) * 4 + 0], s0);
                s1 = fmaf(h4.z, wout_s[(kb + 2) * 4 + 1], s1);
                s2 = fmaf(h4.z, wout_s[(kb + 2) * 4 + 2], s2);
                s0 = fmaf(h4.w, wout_s[(kb + 3) * 4 + 0], s0);
                s1 = fmaf(h4.w, wout_s[(kb + 3) * 4 + 1], s1);
                s2 = fmaf(h4.w, wout_s[(kb + 3) * 4 + 2], s2);
            }
            red[(p * TILE_M + r) * 3 + 0] = s0;
            red[(p * TILE_M + r) * 3 + 1] = s1;
            red[(p * TILE_M + r) * 3 + 2] = s2;
        }
        __syncthreads();
        if (tid < TILE_M) {
            int r = tid;
            float o0 = bout[e * 3 + 0];
            float o1 = bout[e * 3 + 1];
            float o2 = bout[e * 3 + 2];
            #pragma unroll
            for (int p = 0; p < 4; p++) {
                o0 += red[(p * TILE_M + r) * 3 + 0];
                o1 += red[(p * TILE_M + r) * 3 + 1];
                o2 += red[(p * TILE_M + r) * 3 + 2];
            }
            float g = gsm[r * E_EXP + e];
            comb[r * 3 + 0] = fmaf(g, o0, comb[r * 3 + 0]);
            comb[r * 3 + 1] = fmaf(g, o1, comb[r * 3 + 1]);
            comb[r * 3 + 2] = fmaf(g, o2, comb[r * 3 + 2]);
        }
        // next expert's layer-0 __syncthreads orders hA reuse
    }

    __syncthreads();
    if (tid < TILE_M * DOUT) out[n0 * DOUT + tid] = comb[tid];
}

extern "C" void kernel_launch(void* const* d_in, const int* in_sizes, int n_in,
                              void* d_out, int out_size) {
    (void)in_sizes; (void)n_in; (void)out_size;
    const float* x      = (const float*)d_in[0];
    const float* gate_W = (const float*)d_in[1];
    const float* gate_b = (const float*)d_in[2];
    const float* W0     = (const float*)d_in[3];
    const float* b0     = (const float*)d_in[4];
    const float* Wh     = (const float*)d_in[5];
    const float* bh     = (const float*)d_in[6];
    const float* Wout   = (const float*)d_in[7];
    const float* bout   = (const float*)d_in[8];
    float* out = (float*)d_out;

    cudaFuncSetAttribute(moe_siren_kernel,
                         cudaFuncAttributeMaxDynamicSharedMemorySize, SMEM_BYTES);
    moe_siren_kernel<<<NPTS / TILE_M, NTHR, SMEM_BYTES>>>(
        x, gate_W, gate_b, W0, b0, Wh, bh, Wout, bout, out);
}

// round 3
// speedup vs baseline: 1.9316x; 1.9316x over previous
#include <cuda_runtime.h>
#include <cuda_fp16.h>
#include <cstdint>

#define E_EXP 8
#define H_DIM 256
#define NHID  3
#define OMEGA 30.0f
#define NPTS  65536
#define TILE_M 128
#define NTHR  512
#define NMAT  (E_EXP * NHID)

// SMEM layout (bytes)
#define A_STR   528                    // A row stride: 512B data + 16B pad (bank-conflict-free)
#define W_STR   80                     // W chunk row stride: 64B data + 16B pad
#define S_AH    0
#define S_AL    67584                  // 128*528
#define S_WB    135168                 // 2 bufs x (hi 20480 + lo 20480)
#define WBUF_SZ 40960
#define WLO_OFF 20480
#define S_WOUT  217088                 // 256*4 floats
#define S_BIAS  221184                 // 256 floats
#define S_XS    222208                 // 256 floats
#define SMEM_BYTES 223232
// aliased regions:
//   red  (128*4*3 floats = 6144B)  aliases S_AH   (A dead during last-layer reduce)
//   w0s  (768 floats = 3072B)      aliases S_WB   (W bufs dead during layer 0)

// Pre-split transposed weights: [mat][n_out][k_in] fp16
__device__ __half g_Whi[NMAT * H_DIM * H_DIM];
__device__ __half g_Wlo[NMAT * H_DIM * H_DIM];

static __device__ __forceinline__ uint32_t smem_u32(const void* p) {
    uint32_t a;
    asm("{ .reg .u64 t; cvta.to.shared.u64 t, %1; cvt.u32.u64 %0, t; }" : "=r"(a) : "l"(p));
    return a;
}

#define LDSM4(r0, r1, r2, r3, addr) \
    asm volatile("ldmatrix.sync.aligned.m8n8.x4.shared.b16 {%0,%1,%2,%3}, [%4];" \
                 : "=r"(r0), "=r"(r1), "=r"(r2), "=r"(r3) : "r"(addr))

static __device__ __forceinline__ void mma16816(float* c, const uint32_t* a,
                                                uint32_t b0, uint32_t b1) {
    asm volatile("mma.sync.aligned.m16n8k16.row.col.f32.f16.f16.f32 "
                 "{%0,%1,%2,%3}, {%4,%5,%6,%7}, {%8,%9}, {%0,%1,%2,%3};"
                 : "+f"(c[0]), "+f"(c[1]), "+f"(c[2]), "+f"(c[3])
                 : "r"(a[0]), "r"(a[1]), "r"(a[2]), "r"(a[3]), "r"(b0), "r"(b1));
}

#define CP16(dst, src) \
    asm volatile("cp.async.cg.shared.global [%0], [%1], 16;" :: "r"(dst), "l"(src))
#define CP_COMMIT() asm volatile("cp.async.commit_group;")
#define CP_WAIT0()  asm volatile("cp.async.wait_group 0;")
#define CP_WAIT1()  asm volatile("cp.async.wait_group 1;")

// fast sin, all FFMA (validated rel_err 1e-6 in round 1)
static __device__ __forceinline__ float fast_sin(float a) {
    float j = rintf(a * 0.63661977236758134308f);
    int q = (int)j;
    float r = fmaf(j, -1.57079637050628662109375f, a);
    r = fmaf(j, 4.37113883e-8f, r);
    float z = r * r;
    float sp = fmaf(z, -1.95152959e-4f, 8.33216087e-3f);
    sp = fmaf(z, sp, -1.66666546e-1f);
    sp = fmaf(sp * z, r, r);
    float cp = fmaf(z, 2.44331571e-5f, -1.38873163e-3f);
    cp = fmaf(z, cp, 4.16666418e-2f);
    cp = fmaf(z, cp, -5.0e-1f);
    cp = fmaf(z, cp, 1.0f);
    float res = (q & 1) ? cp : sp;
    return (q & 2) ? -res : res;
}

// ---------------- prep: transpose + fp16 hi/lo split ----------------
__global__ void prep_split_kernel(const float* __restrict__ Wh) {
    __shared__ float t[32][33];
    const int mat = blockIdx.z;
    const float* src = Wh + (size_t)mat * 65536;     // [k][n]
    const int n0 = blockIdx.x * 32, k0 = blockIdx.y * 32;
    const int tx = threadIdx.x, ty = threadIdx.y;
    #pragma unroll
    for (int i = 0; i < 32; i += 8)
        t[ty + i][tx] = src[(size_t)(k0 + ty + i) * 256 + (n0 + tx)];
    __syncthreads();
    #pragma unroll
    for (int i = 0; i < 32; i += 8) {
        float w = t[tx][ty + i];
        __half hi = __float2half_rn(w);
        float res = w - __half2float(hi);
        size_t o = (size_t)mat * 65536 + (size_t)(n0 + ty + i) * 256 + (k0 + tx);
        g_Whi[o] = hi;
        g_Wlo[o] = __float2half_rn(res);
    }
}

// ---------------- main kernel ----------------
extern __shared__ char smem[];

__global__ void __launch_bounds__(NTHR, 1)
moe_mma_kernel(const float* __restrict__ x,
               const float* __restrict__ gate_W,
               const float* __restrict__ gate_b,
               const float* __restrict__ W0,
               const float* __restrict__ b0,
               const float* __restrict__ Wh_unused,
               const float* __restrict__ bh,
               const float* __restrict__ Wout,
               const float* __restrict__ bout,
               float* __restrict__ out)
{
    const uint32_t smem0 = smem_u32(smem);
    char*  sc     = smem;
    float* wout_s = (float*)(sc + S_WOUT);
    float* bias_s = (float*)(sc + S_BIAS);
    float* xs     = (float*)(sc + S_XS);
    float* red    = (float*)(sc + S_AH);     // alias
    float* w0s    = (float*)(sc + S_WB);     // alias

    const int tid  = threadIdx.x;
    const int lane = tid & 31;
    const int wid  = tid >> 5;
    const int warp_m = wid >> 2;
    const int warp_n = wid & 3;

    // lane-invariant ldmatrix offsets
    const uint32_t a_base = S_AH
        + (uint32_t)(warp_m * 32 + (lane & 7) + ((lane >> 3) & 1) * 8) * A_STR
        + ((uint32_t)lane >> 4) * 16;
    const uint32_t b_base =
        (uint32_t)(warp_n * 64 + (lane & 7) + ((lane >> 4) & 1) * 8) * W_STR
        + (((uint32_t)lane >> 3) & 1) * 16;

    if (tid < 256) xs[tid] = x[blockIdx.x * 256 + tid];
    __syncthreads();

    // gate softmax (threads < 128 own one point)
    float gts[E_EXP];
    float cb0 = 0.f, cb1 = 0.f, cb2 = 0.f;
    if (tid < TILE_M) {
        float x0 = xs[tid * 2], x1 = xs[tid * 2 + 1];
        float mx = -1e30f;
        #pragma unroll
        for (int e = 0; e < E_EXP; e++) {
            float v = fmaf(x0, __ldg(gate_W + e), fmaf(x1, __ldg(gate_W + 8 + e), __ldg(gate_b + e)));
            gts[e] = v; mx = fmaxf(mx, v);
        }
        float s = 0.f;
        #pragma unroll
        for (int e = 0; e < E_EXP; e++) { gts[e] = expf(gts[e] - mx); s += gts[e]; }
        float inv = 1.0f / s;
        #pragma unroll
        for (int e = 0; e < E_EXP; e++) gts[e] *= inv;
    }

    #pragma unroll 1
    for (int e = 0; e < E_EXP; e++) {
        // stage Wout[e] -> [256][4]; W0/b0 -> w0s[768] (aliases W bufs, idle now)
        if (tid < 256) {
            wout_s[tid * 4 + 0] = __ldg(Wout + e * 768 + tid * 3 + 0);
            wout_s[tid * 4 + 1] = __ldg(Wout + e * 768 + tid * 3 + 1);
            wout_s[tid * 4 + 2] = __ldg(Wout + e * 768 + tid * 3 + 2);
            wout_s[tid * 4 + 3] = 0.f;
        }
        for (int i = tid; i < 768; i += NTHR)
            w0s[i] = (i < 512) ? __ldg(W0 + e * 512 + i) : __ldg(b0 + e * 256 + (i - 512));
        __syncthreads();

        // -------- layer 0 (K=2, fp32) -> A hi/lo in SMEM --------
        {
            const int m = tid >> 2, p = tid & 3;
            const float x0 = xs[m * 2], x1 = xs[m * 2 + 1];
            #pragma unroll 4
            for (int j = 0; j < 32; j++) {
                int c0 = j * 8 + p * 2;
                float z0 = fmaf(x0, w0s[c0],     fmaf(x1, w0s[256 + c0],     w0s[512 + c0]));
                float z1 = fmaf(x0, w0s[c0 + 1], fmaf(x1, w0s[256 + c0 + 1], w0s[512 + c0 + 1]));
                float s0 = fast_sin(OMEGA * z0);
                float s1 = fast_sin(OMEGA * z1);
                __half2 h = __floats2half2_rn(s0, s1);
                __half2 lo = __floats2half2_rn(s0 - __low2float(h), s1 - __high2float(h));
                char* pa = sc + S_AH + m * A_STR + c0 * 2;
                *(uint32_t*)pa = *(uint32_t*)&h;
                *(uint32_t*)(pa + (S_AL - S_AH)) = *(uint32_t*)&lo;
            }
            __syncthreads();
        }

        // -------- hidden layers --------
        #pragma unroll 1
        for (int l = 0; l < NHID; l++) {
            const __half* whg = g_Whi + (size_t)(e * 3 + l) * 65536;
            const __half* wlg = g_Wlo + (size_t)(e * 3 + l) * 65536;
            if (tid < 256) bias_s[tid] = __ldg(bh + (e * 3 + l) * 256 + tid);

            float cacc[2][8][4];
            #pragma unroll
            for (int mt = 0; mt < 2; mt++)
                #pragma unroll
                for (int nt = 0; nt < 8; nt++)
                    #pragma unroll
                    for (int q = 0; q < 4; q++) cacc[mt][nt][q] = 0.f;

            // issue chunk 0
            {
                uint32_t dh = smem0 + S_WB;
                const __half* sh = whg;  const __half* sl = wlg;
                int i0 = tid, i1 = tid + NTHR;
                CP16(dh + (i0 >> 2) * W_STR + (i0 & 3) * 16,           sh + (i0 >> 2) * 256 + (i0 & 3) * 8);
                CP16(dh + WLO_OFF + (i0 >> 2) * W_STR + (i0 & 3) * 16, sl + (i0 >> 2) * 256 + (i0 & 3) * 8);
                CP16(dh + (i1 >> 2) * W_STR + (i1 & 3) * 16,           sh + (i1 >> 2) * 256 + (i1 & 3) * 8);
                CP16(dh + WLO_OFF + (i1 >> 2) * W_STR + (i1 & 3) * 16, sl + (i1 >> 2) * 256 + (i1 & 3) * 8);
                CP_COMMIT();
            }

            #pragma unroll 1
            for (int kc = 0; kc < 8; kc++) {
                const int buf = kc & 1;
                if (kc < 7) {
                    uint32_t dh = smem0 + S_WB + ((kc + 1) & 1) * WBUF_SZ;
                    const __half* sh = whg + (kc + 1) * 32;
                    const __half* sl = wlg + (kc + 1) * 32;
                    int i0 = tid, i1 = tid + NTHR;
                    CP16(dh + (i0 >> 2) * W_STR + (i0 & 3) * 16,           sh + (i0 >> 2) * 256 + (i0 & 3) * 8);
                    CP16(dh + WLO_OFF + (i0 >> 2) * W_STR + (i0 & 3) * 16, sl + (i0 >> 2) * 256 + (i0 & 3) * 8);
                    CP16(dh + (i1 >> 2) * W_STR + (i1 & 3) * 16,           sh + (i1 >> 2) * 256 + (i1 & 3) * 8);
                    CP16(dh + WLO_OFF + (i1 >> 2) * W_STR + (i1 & 3) * 16, sl + (i1 >> 2) * 256 + (i1 & 3) * 8);
                    CP_COMMIT();
                    CP_WAIT1();
                } else {
                    CP_WAIT0();
                }
                __syncthreads();

                const uint32_t wb = smem0 + S_WB + buf * WBUF_SZ;
                #pragma unroll
                for (int k2 = 0; k2 < 2; k2++) {
                    const int kstep = kc * 2 + k2;
                    uint32_t ahi[2][4], alo[2][4];
                    #pragma unroll
                    for (int mt = 0; mt < 2; mt++) {
                        uint32_t aa = smem0 + a_base + mt * (16 * A_STR) + kstep * 32;
                        LDSM4(ahi[mt][0], ahi[mt][1], ahi[mt][2], ahi[mt][3], aa);
                        LDSM4(alo[mt][0], alo[mt][1], alo[mt][2], alo[mt][3], aa + (S_AL - S_AH));
                    }
                    #pragma unroll
                    for (int np = 0; np < 4; np++) {
                        uint32_t bo = wb + b_base + np * (16 * W_STR) + k2 * 32;
                        uint32_t bh0, bh1, bh2, bh3, bl0, bl1, bl2, bl3;
                        LDSM4(bh0, bh1, bh2, bh3, bo);
                        LDSM4(bl0, bl1, bl2, bl3, bo + WLO_OFF);
                        #pragma unroll
                        for (int mt = 0; mt < 2; mt++) {
                            mma16816(cacc[mt][np * 2],     ahi[mt], bh0, bh1);
                            mma16816(cacc[mt][np * 2],     alo[mt], bh0, bh1);
                            mma16816(cacc[mt][np * 2],     ahi[mt], bl0, bl1);
                            mma16816(cacc[mt][np * 2 + 1], ahi[mt], bh2, bh3);
                            mma16816(cacc[mt][np * 2 + 1], alo[mt], bh2, bh3);
                            mma16816(cacc[mt][np * 2 + 1], ahi[mt], bl2, bl3);
                        }
                    }
                }
                __syncthreads();
            }

            if (l < NHID - 1) {
                // bias + sin + fp16 split -> A bufs for next layer
                #pragma unroll
                for (int mt = 0; mt < 2; mt++) {
                    int r0 = warp_m * 32 + mt * 16 + (lane >> 2);
                    #pragma unroll
                    for (int nt = 0; nt < 8; nt++) {
                        int n0 = warp_n * 64 + nt * 8 + 2 * (lane & 3);
                        float2 bb = *(const float2*)(bias_s + n0);
                        float* cc = cacc[mt][nt];
                        float s00 = fast_sin(OMEGA * (cc[0] + bb.x));
                        float s01 = fast_sin(OMEGA * (cc[1] + bb.y));
                        float s10 = fast_sin(OMEGA * (cc[2] + bb.x));
                        float s11 = fast_sin(OMEGA * (cc[3] + bb.y));
                        __half2 h0 = __floats2half2_rn(s00, s01);
                        __half2 h1 = __floats2half2_rn(s10, s11);
                        __half2 l0 = __floats2half2_rn(s00 - __low2float(h0), s01 - __high2float(h0));
                        __half2 l1 = __floats2half2_rn(s10 - __low2float(h1), s11 - __high2float(h1));
                        char* p0 = sc + S_AH + r0 * A_STR + n0 * 2;
                        char* p1 = p0 + 8 * A_STR;
                        *(uint32_t*)p0 = *(uint32_t*)&h0;
                        *(uint32_t*)p1 = *(uint32_t*)&h1;
                        *(uint32_t*)(p0 + (S_AL - S_AH)) = *(uint32_t*)&l0;
                        *(uint32_t*)(p1 + (S_AL - S_AH)) = *(uint32_t*)&l1;
                    }
                }
                __syncthreads();
            } else {
                // last layer: bias + sin + Wout dot + cross-warp reduce + gated combine
                float o[4][3];
                #pragma unroll
                for (int i = 0; i < 4; i++)
                    #pragma unroll
                    for (int c3 = 0; c3 < 3; c3++) o[i][c3] = 0.f;
                #pragma unroll
                for (int mt = 0; mt < 2; mt++) {
                    #pragma unroll
                    for (int nt = 0; nt < 8; nt++) {
                        int n0 = warp_n * 64 + nt * 8 + 2 * (lane & 3);
                        float2 bb = *(const float2*)(bias_s + n0);
                        float* cc = cacc[mt][nt];
                        float s00 = fast_sin(OMEGA * (cc[0] + bb.x));
                        float s01 = fast_sin(OMEGA * (cc[1] + bb.y));
                        float s10 = fast_sin(OMEGA * (cc[2] + bb.x));
                        float s11 = fast_sin(OMEGA * (cc[3] + bb.y));
                        const float* wA = wout_s + n0 * 4;
                        const float* wB = wout_s + (n0 + 1) * 4;
                        #pragma unroll
                        for (int c3 = 0; c3 < 3; c3++) {
                            o[mt * 2 + 0][c3] = fmaf(s00, wA[c3], fmaf(s01, wB[c3], o[mt * 2 + 0][c3]));
                            o[mt * 2 + 1][c3] = fmaf(s10, wA[c3], fmaf(s11, wB[c3], o[mt * 2 + 1][c3]));
                        }
                    }
                }
                #pragma unroll
                for (int i = 0; i < 4; i++)
                    #pragma unroll
                    for (int c3 = 0; c3 < 3; c3++) {
                        float v = o[i][c3];
                        v += __shfl_xor_sync(0xFFFFFFFF, v, 1);
                        v += __shfl_xor_sync(0xFFFFFFFF, v, 2);
                        o[i][c3] = v;
                    }
                if ((lane & 3) == 0) {
                    int q = lane >> 2;
                    #pragma unroll
                    for (int i = 0; i < 4; i++) {
                        int r = warp_m * 32 + (i >> 1) * 16 + (i & 1) * 8 + q;
                        #pragma unroll
                        for (int c3 = 0; c3 < 3; c3++)
                            red[r * 12 + warp_n * 3 + c3] = o[i][c3];
                    }
                }
                __syncthreads();
                if (tid < TILE_M) {
                    float g = gts[e];
                    #pragma unroll
                    for (int c3 = 0; c3 < 3; c3++) {
                        float oc = __ldg(bout + e * 3 + c3)
                                 + red[tid * 12 + c3] + red[tid * 12 + 3 + c3]
                                 + red[tid * 12 + 6 + c3] + red[tid * 12 + 9 + c3];
                        if (c3 == 0) cb0 = fmaf(g, oc, cb0);
                        else if (c3 == 1) cb1 = fmaf(g, oc, cb1);
                        else cb2 = fmaf(g, oc, cb2);
                    }
                }
                __syncthreads();   // red (A alias) consumed before next expert's layer 0
            }
        }
    }

    if (tid < TILE_M) {
        int r = blockIdx.x * TILE_M + tid;
        out[r * 3 + 0] = cb0;
        out[r * 3 + 1] = cb1;
        out[r * 3 + 2] = cb2;
    }
}

extern "C" void kernel_launch(void* const* d_in, const int* in_sizes, int n_in,
                              void* d_out, int out_size) {
    (void)in_sizes; (void)n_in; (void)out_size;
    const float* x      = (const float*)d_in[0];
    const float* gate_W = (const float*)d_in[1];
    const float* gate_b = (const float*)d_in[2];
    const float* W0     = (const float*)d_in[3];
    const float* b0     = (const float*)d_in[4];
    const float* Wh     = (const float*)d_in[5];
    const float* bh     = (const float*)d_in[6];
    const float* Wout   = (const float*)d_in[7];
    const float* bout   = (const float*)d_in[8];
    float* out = (float*)d_out;

    dim3 pg(8, 8, NMAT), pb(32, 8);
    prep_split_kernel<<<pg, pb>>>(Wh);

    cudaFuncSetAttribute(moe_mma_kernel,
                         cudaFuncAttributeMaxDynamicSharedMemorySize, SMEM_BYTES);
    moe_mma_kernel<<<NPTS / TILE_M, NTHR, SMEM_BYTES>>>(
        x, gate_W, gate_b, W0, b0, Wh, bh, Wout, bout, out);
}

// round 4
// speedup vs baseline: 2.0114x; 1.0413x over previous
#include <cuda_runtime.h>
#include <cuda_fp16.h>
#include <cstdint>

#define E_EXP 8
#define H_DIM 256
#define NHID  3
#define OMEGA 30.0f
#define NPTS  65536
#define TILE_M 64
#define NTHR  256
#define NMAT  (E_EXP * NHID)

// ---- SMEM layout (bytes), all XOR-swizzled, no padding ----
#define S_A     0              // A_hi: 64 rows x 512B
#define AL_OFF  32768          // A_lo
#define S_WB    65536          // 2 bufs x (hi 8KB + lo 8KB)
#define WBUF_SZ 16384
#define WLO_OFF 8192
#define S_WOUT  98304          // 256*4 floats
#define S_BIAS  102400         // 256 floats
#define S_XS    103424         // 128 floats (padded to 1KB)
#define SMEM_BYTES 104448      // 102KB -> 2 CTAs/SM
// aliases: red (64*12 floats = 3KB) over S_A; w0s (768 floats) over S_WB

// Pre-split transposed weights: [mat][n_out][k_in] fp16
__device__ __half g_Whi[NMAT * H_DIM * H_DIM];
__device__ __half g_Wlo[NMAT * H_DIM * H_DIM];

static __device__ __forceinline__ uint32_t smem_u32(const void* p) {
    uint32_t a;
    asm("{ .reg .u64 t; cvta.to.shared.u64 t, %1; cvt.u32.u64 %0, t; }" : "=r"(a) : "l"(p));
    return a;
}

// A swizzle: row m (0..63) of 32 16B-units; unit low-3 bits XOR row low-3 bits
static __device__ __forceinline__ uint32_t a_sw(uint32_t m, uint32_t u) {
    return m * 512u + ((((u ^ m) & 7u) | (u & 24u)) << 4);
}
// W swizzle: row n (0..255) of 2 16B-units; unit bit XOR (n>>2)&1
static __device__ __forceinline__ uint32_t w_sw(uint32_t n, uint32_t u) {
    return n * 32u + (((u ^ (n >> 2)) & 1u) << 4);
}

#define LDSM4(r0, r1, r2, r3, addr) \
    asm volatile("ldmatrix.sync.aligned.m8n8.x4.shared.b16 {%0,%1,%2,%3}, [%4];" \
                 : "=r"(r0), "=r"(r1), "=r"(r2), "=r"(r3) : "r"(addr))

static __device__ __forceinline__ void mma16816(float* c, const uint32_t* a,
                                                uint32_t b0, uint32_t b1) {
    asm volatile("mma.sync.aligned.m16n8k16.row.col.f32.f16.f16.f32 "
                 "{%0,%1,%2,%3}, {%4,%5,%6,%7}, {%8,%9}, {%0,%1,%2,%3};"
                 : "+f"(c[0]), "+f"(c[1]), "+f"(c[2]), "+f"(c[3])
                 : "r"(a[0]), "r"(a[1]), "r"(a[2]), "r"(a[3]), "r"(b0), "r"(b1));
}

#define CP16(dst, src) \
    asm volatile("cp.async.cg.shared.global [%0], [%1], 16;" :: "r"(dst), "l"(src))
#define CP_COMMIT() asm volatile("cp.async.commit_group;")
#define CP_WAIT0()  asm volatile("cp.async.wait_group 0;")
#define CP_WAIT1()  asm volatile("cp.async.wait_group 1;")

// fast sin, all FFMA (validated rel_err ~1e-6)
static __device__ __forceinline__ float fast_sin(float a) {
    float j = rintf(a * 0.63661977236758134308f);
    int q = (int)j;
    float r = fmaf(j, -1.57079637050628662109375f, a);
    r = fmaf(j, 4.37113883e-8f, r);
    float z = r * r;
    float sp = fmaf(z, -1.95152959e-4f, 8.33216087e-3f);
    sp = fmaf(z, sp, -1.66666546e-1f);
    sp = fmaf(sp * z, r, r);
    float cp = fmaf(z, 2.44331571e-5f, -1.38873163e-3f);
    cp = fmaf(z, cp, 4.16666418e-2f);
    cp = fmaf(z, cp, -5.0e-1f);
    cp = fmaf(z, cp, 1.0f);
    float res = (q & 1) ? cp : sp;
    return (q & 2) ? -res : res;
}

// ---------------- prep: transpose + fp16 hi/lo split ----------------
__global__ void prep_split_kernel(const float* __restrict__ Wh) {
    __shared__ float t[32][33];
    const int mat = blockIdx.z;
    const float* src = Wh + (size_t)mat * 65536;     // [k][n]
    const int n0 = blockIdx.x * 32, k0 = blockIdx.y * 32;
    const int tx = threadIdx.x, ty = threadIdx.y;
    #pragma unroll
    for (int i = 0; i < 32; i += 8)
        t[ty + i][tx] = src[(size_t)(k0 + ty + i) * 256 + (n0 + tx)];
    __syncthreads();
    #pragma unroll
    for (int i = 0; i < 32; i += 8) {
        float w = t[tx][ty + i];
        __half hi = __float2half_rn(w);
        float res = w - __half2float(hi);
        size_t o = (size_t)mat * 65536 + (size_t)(n0 + ty + i) * 256 + (k0 + tx);
        g_Whi[o] = hi;
        g_Wlo[o] = __float2half_rn(res);
    }
}

// ---------------- main kernel ----------------
extern __shared__ char smem[];

__global__ void __launch_bounds__(NTHR, 2)
moe_mma_kernel(const float* __restrict__ x,
               const float* __restrict__ gate_W,
               const float* __restrict__ gate_b,
               const float* __restrict__ W0,
               const float* __restrict__ b0,
               const float* __restrict__ Wh_unused,
               const float* __restrict__ bh,
               const float* __restrict__ Wout,
               const float* __restrict__ bout,
               float* __restrict__ out)
{
    const uint32_t smem0 = smem_u32(smem);
    char*  sc     = smem;
    float* wout_s = (float*)(sc + S_WOUT);
    float* bias_s = (float*)(sc + S_BIAS);
    float* xs     = (float*)(sc + S_XS);
    float* red    = (float*)(sc + S_A);      // alias (A dead then)
    float* w0s    = (float*)(sc + S_WB);     // alias (W bufs dead then)

    const int tid  = threadIdx.x;
    const int lane = tid & 31;
    const int wid  = tid >> 5;
    const int warp_m = wid >> 2;             // 0..1
    const int warp_n = wid & 3;              // 0..3

    const int m0l = warp_m * 32 + (lane & 15);           // A ldmatrix row (per mt +16)
    const int bnl = warp_n * 64 + (lane & 7) + ((lane >> 4) & 1) * 8; // B row base (per np +16)
    const uint32_t bul = (lane >> 3) & 1;                // B k-unit

    if (tid < 128) xs[tid] = x[blockIdx.x * 128 + tid];
    __syncthreads();

    // gate softmax (threads < 64 own one point)
    float gts[E_EXP];
    float cb0 = 0.f, cb1 = 0.f, cb2 = 0.f;
    if (tid < TILE_M) {
        float x0 = xs[tid * 2], x1 = xs[tid * 2 + 1];
        float mx = -1e30f;
        #pragma unroll
        for (int e = 0; e < E_EXP; e++) {
            float v = fmaf(x0, __ldg(gate_W + e), fmaf(x1, __ldg(gate_W + 8 + e), __ldg(gate_b + e)));
            gts[e] = v; mx = fmaxf(mx, v);
        }
        float s = 0.f;
        #pragma unroll
        for (int e = 0; e < E_EXP; e++) { gts[e] = expf(gts[e] - mx); s += gts[e]; }
        float inv = 1.0f / s;
        #pragma unroll
        for (int e = 0; e < E_EXP; e++) gts[e] *= inv;
    }

    #pragma unroll 1
    for (int e = 0; e < E_EXP; e++) {
        // stage Wout[e] -> [256][4]; W0/b0 -> w0s[768] (aliases W bufs)
        wout_s[tid * 4 + 0] = __ldg(Wout + e * 768 + tid * 3 + 0);
        wout_s[tid * 4 + 1] = __ldg(Wout + e * 768 + tid * 3 + 1);
        wout_s[tid * 4 + 2] = __ldg(Wout + e * 768 + tid * 3 + 2);
        wout_s[tid * 4 + 3] = 0.f;
        for (int i = tid; i < 768; i += NTHR)
            w0s[i] = (i < 512) ? __ldg(W0 + e * 512 + i) : __ldg(b0 + e * 256 + (i - 512));
        __syncthreads();

        // -------- layer 0 (K=2, fp32) -> A hi/lo in SMEM --------
        {
            const int m = tid >> 2, p = tid & 3;
            const float x0 = xs[m * 2], x1 = xs[m * 2 + 1];
            #pragma unroll 4
            for (int j = 0; j < 32; j++) {
                int c0 = j * 8 + p * 2;
                float z0 = fmaf(x0, w0s[c0],     fmaf(x1, w0s[256 + c0],     w0s[512 + c0]));
                float z1 = fmaf(x0, w0s[c0 + 1], fmaf(x1, w0s[256 + c0 + 1], w0s[512 + c0 + 1]));
                float s0 = fast_sin(OMEGA * z0);
                float s1 = fast_sin(OMEGA * z1);
                __half2 h = __floats2half2_rn(s0, s1);
                __half2 lo = __floats2half2_rn(s0 - __low2float(h), s1 - __high2float(h));
                uint32_t off = a_sw(m, j) + p * 4;
                *(uint32_t*)(sc + S_A + off) = *(uint32_t*)&h;
                *(uint32_t*)(sc + S_A + off + AL_OFF) = *(uint32_t*)&lo;
            }
            __syncthreads();
        }

        // -------- hidden layers --------
        #pragma unroll 1
        for (int l = 0; l < NHID; l++) {
            const __half* whg = g_Whi + (size_t)(e * 3 + l) * 65536;
            const __half* wlg = g_Wlo + (size_t)(e * 3 + l) * 65536;
            bias_s[tid] = __ldg(bh + (e * 3 + l) * 256 + tid);

            float cacc[2][8][4];
            #pragma unroll
            for (int mt = 0; mt < 2; mt++)
                #pragma unroll
                for (int nt = 0; nt < 8; nt++)
                    #pragma unroll
                    for (int q = 0; q < 4; q++) cacc[mt][nt][q] = 0.f;

            // cp.async of one chunk (kc): 1024 16B units, 4 per thread
            const int un = tid >> 1;            // n-row for t=0,1 pair base
            const int uu = tid & 1;             // k-unit
            // issue chunk 0
            {
                uint32_t db = smem0 + S_WB;
                CP16(db + w_sw(un, uu),                      whg + un * 256 + uu * 8);
                CP16(db + w_sw(un + 128, uu),                whg + (un + 128) * 256 + uu * 8);
                CP16(db + WLO_OFF + w_sw(un, uu),            wlg + un * 256 + uu * 8);
                CP16(db + WLO_OFF + w_sw(un + 128, uu),      wlg + (un + 128) * 256 + uu * 8);
                CP_COMMIT();
            }

            #pragma unroll 1
            for (int kc = 0; kc < 16; kc++) {
                const int buf = kc & 1;
                if (kc < 15) {
                    uint32_t db = smem0 + S_WB + ((kc + 1) & 1) * WBUF_SZ;
                    const __half* sh = whg + (kc + 1) * 16;
                    const __half* sl = wlg + (kc + 1) * 16;
                    CP16(db + w_sw(un, uu),                 sh + un * 256 + uu * 8);
                    CP16(db + w_sw(un + 128, uu),           sh + (un + 128) * 256 + uu * 8);
                    CP16(db + WLO_OFF + w_sw(un, uu),       sl + un * 256 + uu * 8);
                    CP16(db + WLO_OFF + w_sw(un + 128, uu), sl + (un + 128) * 256 + uu * 8);
                    CP_COMMIT();
                    CP_WAIT1();
                } else {
                    CP_WAIT0();
                }
                __syncthreads();

                // A fragments for this k16
                uint32_t ahi[2][4], alo[2][4];
                #pragma unroll
                for (int mt = 0; mt < 2; mt++) {
                    uint32_t ml = (uint32_t)(m0l + mt * 16);
                    uint32_t u = (uint32_t)(kc * 2) + (lane >> 4);
                    uint32_t aa = smem0 + S_A + a_sw(ml, u);
                    LDSM4(ahi[mt][0], ahi[mt][1], ahi[mt][2], ahi[mt][3], aa);
                    LDSM4(alo[mt][0], alo[mt][1], alo[mt][2], alo[mt][3], aa + AL_OFF);
                }
                const uint32_t wb = smem0 + S_WB + buf * WBUF_SZ;
                #pragma unroll
                for (int np = 0; np < 4; np++) {
                    uint32_t n = (uint32_t)(bnl + np * 16);
                    uint32_t bo = wb + w_sw(n, bul);
                    uint32_t bh0, bh1, bh2, bh3, bl0, bl1, bl2, bl3;
                    LDSM4(bh0, bh1, bh2, bh3, bo);
                    LDSM4(bl0, bl1, bl2, bl3, bo + WLO_OFF);
                    #pragma unroll
                    for (int mt = 0; mt < 2; mt++) {
                        mma16816(cacc[mt][np * 2],     ahi[mt], bh0, bh1);
                        mma16816(cacc[mt][np * 2],     alo[mt], bh0, bh1);
                        mma16816(cacc[mt][np * 2],     ahi[mt], bl0, bl1);
                        mma16816(cacc[mt][np * 2 + 1], ahi[mt], bh2, bh3);
                        mma16816(cacc[mt][np * 2 + 1], alo[mt], bh2, bh3);
                        mma16816(cacc[mt][np * 2 + 1], ahi[mt], bl2, bl3);
                    }
                }
                __syncthreads();
            }

            if (l < NHID - 1) {
                // bias + sin + fp16 split -> A bufs for next layer
                #pragma unroll
                for (int mt = 0; mt < 2; mt++) {
                    int r0 = warp_m * 32 + mt * 16 + (lane >> 2);
                    #pragma unroll
                    for (int nt = 0; nt < 8; nt++) {
                        int n0 = warp_n * 64 + nt * 8 + 2 * (lane & 3);
                        uint32_t u = (uint32_t)(warp_n * 8 + nt);
                        float2 bb = *(const float2*)(bias_s + n0);
                        float* cc = cacc[mt][nt];
                        float s00 = fast_sin(OMEGA * (cc[0] + bb.x));
                        float s01 = fast_sin(OMEGA * (cc[1] + bb.y));
                        float s10 = fast_sin(OMEGA * (cc[2] + bb.x));
                        float s11 = fast_sin(OMEGA * (cc[3] + bb.y));
                        __half2 h0 = __floats2half2_rn(s00, s01);
                        __half2 h1 = __floats2half2_rn(s10, s11);
                        __half2 l0 = __floats2half2_rn(s00 - __low2float(h0), s01 - __high2float(h0));
                        __half2 l1 = __floats2half2_rn(s10 - __low2float(h1), s11 - __high2float(h1));
                        uint32_t o0 = a_sw((uint32_t)r0, u) + (lane & 3) * 4;
                        uint32_t o1 = a_sw((uint32_t)(r0 + 8), u) + (lane & 3) * 4;
                        *(uint32_t*)(sc + S_A + o0) = *(uint32_t*)&h0;
                        *(uint32_t*)(sc + S_A + o1) = *(uint32_t*)&h1;
                        *(uint32_t*)(sc + S_A + o0 + AL_OFF) = *(uint32_t*)&l0;
                        *(uint32_t*)(sc + S_A + o1 + AL_OFF) = *(uint32_t*)&l1;
                    }
                }
                __syncthreads();
            } else {
                // last layer: bias + sin + Wout dot + reduce + gated combine
                float o[4][3];
                #pragma unroll
                for (int i = 0; i < 4; i++)
                    #pragma unroll
                    for (int c3 = 0; c3 < 3; c3++) o[i][c3] = 0.f;
                #pragma unroll
                for (int mt = 0; mt < 2; mt++) {
                    #pragma unroll
                    for (int nt = 0; nt < 8; nt++) {
                        int n0 = warp_n * 64 + nt * 8 + 2 * (lane & 3);
                        float2 bb = *(const float2*)(bias_s + n0);
                        float* cc = cacc[mt][nt];
                        float s00 = fast_sin(OMEGA * (cc[0] + bb.x));
                        float s01 = fast_sin(OMEGA * (cc[1] + bb.y));
                        float s10 = fast_sin(OMEGA * (cc[2] + bb.x));
                        float s11 = fast_sin(OMEGA * (cc[3] + bb.y));
                        const float* wA = wout_s + n0 * 4;
                        const float* wB = wout_s + (n0 + 1) * 4;
                        #pragma unroll
                        for (int c3 = 0; c3 < 3; c3++) {
                            o[mt * 2 + 0][c3] = fmaf(s00, wA[c3], fmaf(s01, wB[c3], o[mt * 2 + 0][c3]));
                            o[mt * 2 + 1][c3] = fmaf(s10, wA[c3], fmaf(s11, wB[c3], o[mt * 2 + 1][c3]));
                        }
                    }
                }
                #pragma unroll
                for (int i = 0; i < 4; i++)
                    #pragma unroll
                    for (int c3 = 0; c3 < 3; c3++) {
                        float v = o[i][c3];
                        v += __shfl_xor_sync(0xFFFFFFFF, v, 1);
                        v += __shfl_xor_sync(0xFFFFFFFF, v, 2);
                        o[i][c3] = v;
                    }
                __syncthreads();   // A reads done before red (alias) writes
                if ((lane & 3) == 0) {
                    int q = lane >> 2;
                    #pragma unroll
                    for (int i = 0; i < 4; i++) {
                        int r = warp_m * 32 + (i >> 1) * 16 + (i & 1) * 8 + q;
                        #pragma unroll
                        for (int c3 = 0; c3 < 3; c3++)
                            red[r * 12 + warp_n * 3 + c3] = o[i][c3];
                    }
                }
                __syncthreads();
                if (tid < TILE_M) {
                    float g = gts[e];
                    float oc0 = __ldg(bout + e * 3 + 0)
                              + red[tid * 12 + 0] + red[tid * 12 + 3] + red[tid * 12 + 6] + red[tid * 12 + 9];
                    float oc1 = __ldg(bout + e * 3 + 1)
                              + red[tid * 12 + 1] + red[tid * 12 + 4] + red[tid * 12 + 7] + red[tid * 12 + 10];
                    float oc2 = __ldg(bout + e * 3 + 2)
                              + red[tid * 12 + 2] + red[tid * 12 + 5] + red[tid * 12 + 8] + red[tid * 12 + 11];
                    cb0 = fmaf(g, oc0, cb0);
                    cb1 = fmaf(g, oc1, cb1);
                    cb2 = fmaf(g, oc2, cb2);
                }
                __syncthreads();   // red consumed before next expert's layer 0
            }
        }
    }

    if (tid < TILE_M) {
        int r = blockIdx.x * TILE_M + tid;
        out[r * 3 + 0] = cb0;
        out[r * 3 + 1] = cb1;
        out[r * 3 + 2] = cb2;
    }
}

extern "C" void kernel_launch(void* const* d_in, const int* in_sizes, int n_in,
                              void* d_out, int out_size) {
    (void)in_sizes; (void)n_in; (void)out_size;
    const float* x      = (const float*)d_in[0];
    const float* gate_W = (const float*)d_in[1];
    const float* gate_b = (const float*)d_in[2];
    const float* W0     = (const float*)d_in[3];
    const float* b0     = (const float*)d_in[4];
    const float* Wh     = (const float*)d_in[5];
    const float* bh     = (const float*)d_in[6];
    const float* Wout   = (const float*)d_in[7];
    const float* bout   = (const float*)d_in[8];
    float* out = (float*)d_out;

    dim3 pg(8, 8, NMAT), pb(32, 8);
    prep_split_kernel<<<pg, pb>>>(Wh);

    cudaFuncSetAttribute(moe_mma_kernel,
                         cudaFuncAttributeMaxDynamicSharedMemorySize, SMEM_BYTES);
    moe_mma_kernel<<<NPTS / TILE_M, NTHR, SMEM_BYTES>>>(
        x, gate_W, gate_b, W0, b0, Wh, bh, Wout, bout, out);
}

// round 5
// speedup vs baseline: 2.4802x; 1.2330x over previous
#include <cuda_runtime.h>
#include <cuda_fp16.h>
#include <cstdint>

#define E_EXP 8
#define H_DIM 256
#define NHID  3
#define OMEGA 30.0f
#define NPTS  65536
#define TILE_M 64
#define NTHR  256
#define NMAT  (E_EXP * NHID)

// ---- SMEM layout (bytes), XOR-swizzled, no padding ----
#define S_A     0              // A_hi: 64 rows x 512B
#define AL_OFF  32768          // A_lo
#define S_WB    65536          // 2 bufs x 8KB (hi only)
#define WBUF_SZ 8192
#define S_WOUT  81920          // 256*4 floats
#define S_BIAS  86016          // 256 floats
#define S_XS    87040          // 128 floats (pad to 1KB)
#define SMEM_BYTES 88064       // -> 2 CTAs/SM (reg-bound)
// aliases: red (64*12 floats) over S_A; w0s (768 floats) over S_WB

// Pre-transposed fp16 weights: [mat][n_out][k_in]
__device__ __half g_Whi[NMAT * H_DIM * H_DIM];

static __device__ __forceinline__ uint32_t smem_u32(const void* p) {
    uint32_t a;
    asm("{ .reg .u64 t; cvta.to.shared.u64 t, %1; cvt.u32.u64 %0, t; }" : "=r"(a) : "l"(p));
    return a;
}

// A swizzle: row m (0..63) x 32 16B-units; unit low-3 bits XOR row low-3 bits
static __device__ __forceinline__ uint32_t a_sw(uint32_t m, uint32_t u) {
    return m * 512u + ((((u ^ m) & 7u) | (u & 24u)) << 4);
}
// W swizzle: row n (0..255) x 2 16B-units; unit bit XOR (n>>2)&1
static __device__ __forceinline__ uint32_t w_sw(uint32_t n, uint32_t u) {
    return n * 32u + (((u ^ (n >> 2)) & 1u) << 4);
}

#define LDSM4(r0, r1, r2, r3, addr) \
    asm volatile("ldmatrix.sync.aligned.m8n8.x4.shared.b16 {%0,%1,%2,%3}, [%4];" \
                 : "=r"(r0), "=r"(r1), "=r"(r2), "=r"(r3) : "r"(addr))

static __device__ __forceinline__ void mma16816(float* c, const uint32_t* a,
                                                uint32_t b0, uint32_t b1) {
    asm volatile("mma.sync.aligned.m16n8k16.row.col.f32.f16.f16.f32 "
                 "{%0,%1,%2,%3}, {%4,%5,%6,%7}, {%8,%9}, {%0,%1,%2,%3};"
                 : "+f"(c[0]), "+f"(c[1]), "+f"(c[2]), "+f"(c[3])
                 : "r"(a[0]), "r"(a[1]), "r"(a[2]), "r"(a[3]), "r"(b0), "r"(b1));
}

#define CP16(dst, src) \
    asm volatile("cp.async.cg.shared.global [%0], [%1], 16;" :: "r"(dst), "l"(src))
#define CP_COMMIT() asm volatile("cp.async.commit_group;")
#define CP_WAIT0()  asm volatile("cp.async.wait_group 0;")
#define CP_WAIT1()  asm volatile("cp.async.wait_group 1;")

// fast sin, all FFMA (validated rel_err ~1e-6)
static __device__ __forceinline__ float fast_sin(float a) {
    float j = rintf(a * 0.63661977236758134308f);
    int q = (int)j;
    float r = fmaf(j, -1.57079637050628662109375f, a);
    r = fmaf(j, 4.37113883e-8f, r);
    float z = r * r;
    float sp = fmaf(z, -1.95152959e-4f, 8.33216087e-3f);
    sp = fmaf(z, sp, -1.66666546e-1f);
    sp = fmaf(sp * z, r, r);
    float cp = fmaf(z, 2.44331571e-5f, -1.38873163e-3f);
    cp = fmaf(z, cp, 4.16666418e-2f);
    cp = fmaf(z, cp, -5.0e-1f);
    cp = fmaf(z, cp, 1.0f);
    float res = (q & 1) ? cp : sp;
    return (q & 2) ? -res : res;
}

// ---------------- prep: transpose to [n][k] fp16 ----------------
__global__ void prep_split_kernel(const float* __restrict__ Wh) {
    __shared__ float t[32][33];
    const int mat = blockIdx.z;
    const float* src = Wh + (size_t)mat * 65536;     // [k][n]
    const int n0 = blockIdx.x * 32, k0 = blockIdx.y * 32;
    const int tx = threadIdx.x, ty = threadIdx.y;
    #pragma unroll
    for (int i = 0; i < 32; i += 8)
        t[ty + i][tx] = src[(size_t)(k0 + ty + i) * 256 + (n0 + tx)];
    __syncthreads();
    #pragma unroll
    for (int i = 0; i < 32; i += 8) {
        float w = t[tx][ty + i];
        size_t o = (size_t)mat * 65536 + (size_t)(n0 + ty + i) * 256 + (k0 + tx);
        g_Whi[o] = __float2half_rn(w);
    }
}

// ---------------- main kernel ----------------
extern __shared__ char smem[];

__global__ void __launch_bounds__(NTHR, 2)
moe_mma_kernel(const float* __restrict__ x,
               const float* __restrict__ gate_W,
               const float* __restrict__ gate_b,
               const float* __restrict__ W0,
               const float* __restrict__ b0,
               const float* __restrict__ Wh_unused,
               const float* __restrict__ bh,
               const float* __restrict__ Wout,
               const float* __restrict__ bout,
               float* __restrict__ out)
{
    const uint32_t smem0 = smem_u32(smem);
    char*  sc     = smem;
    float* wout_s = (float*)(sc + S_WOUT);
    float* bias_s = (float*)(sc + S_BIAS);
    float* xs     = (float*)(sc + S_XS);
    float* red    = (float*)(sc + S_A);      // alias (A dead then)
    float* w0s    = (float*)(sc + S_WB);     // alias (W bufs dead then)

    const int tid  = threadIdx.x;
    const int lane = tid & 31;
    const int wid  = tid >> 5;
    const int warp_m = wid >> 2;             // 0..1
    const int warp_n = wid & 3;              // 0..3

    const int m0l = warp_m * 32 + (lane & 15);                       // A ldmatrix row
    const int bnl = warp_n * 64 + (lane & 7) + ((lane >> 4) & 1) * 8; // B row base
    const uint32_t bul = (lane >> 3) & 1;                            // B k-unit

    if (tid < 128) xs[tid] = x[blockIdx.x * 128 + tid];
    __syncthreads();

    // gate softmax (threads < 64 own one point)
    float gts[E_EXP];
    float cb0 = 0.f, cb1 = 0.f, cb2 = 0.f;
    if (tid < TILE_M) {
        float x0 = xs[tid * 2], x1 = xs[tid * 2 + 1];
        float mx = -1e30f;
        #pragma unroll
        for (int e = 0; e < E_EXP; e++) {
            float v = fmaf(x0, __ldg(gate_W + e), fmaf(x1, __ldg(gate_W + 8 + e), __ldg(gate_b + e)));
            gts[e] = v; mx = fmaxf(mx, v);
        }
        float s = 0.f;
        #pragma unroll
        for (int e = 0; e < E_EXP; e++) { gts[e] = expf(gts[e] - mx); s += gts[e]; }
        float inv = 1.0f / s;
        #pragma unroll
        for (int e = 0; e < E_EXP; e++) gts[e] *= inv;
    }

    #pragma unroll 1
    for (int e = 0; e < E_EXP; e++) {
        // stage Wout[e] -> [256][4]; W0/b0 -> w0s[768] (aliases W bufs)
        wout_s[tid * 4 + 0] = __ldg(Wout + e * 768 + tid * 3 + 0);
        wout_s[tid * 4 + 1] = __ldg(Wout + e * 768 + tid * 3 + 1);
        wout_s[tid * 4 + 2] = __ldg(Wout + e * 768 + tid * 3 + 2);
        wout_s[tid * 4 + 3] = 0.f;
        for (int i = tid; i < 768; i += NTHR)
            w0s[i] = (i < 512) ? __ldg(W0 + e * 512 + i) : __ldg(b0 + e * 256 + (i - 512));
        __syncthreads();

        // -------- layer 0 (K=2, fp32) -> A hi/lo in SMEM --------
        {
            const int m = tid >> 2, p = tid & 3;
            const float x0 = xs[m * 2], x1 = xs[m * 2 + 1];
            #pragma unroll 4
            for (int j = 0; j < 32; j++) {
                int c0 = j * 8 + p * 2;
                float z0 = fmaf(x0, w0s[c0],     fmaf(x1, w0s[256 + c0],     w0s[512 + c0]));
                float z1 = fmaf(x0, w0s[c0 + 1], fmaf(x1, w0s[256 + c0 + 1], w0s[512 + c0 + 1]));
                float s0 = fast_sin(OMEGA * z0);
                float s1 = fast_sin(OMEGA * z1);
                __half2 h = __floats2half2_rn(s0, s1);
                __half2 lo = __floats2half2_rn(s0 - __low2float(h), s1 - __high2float(h));
                uint32_t off = a_sw(m, j) + p * 4;
                *(uint32_t*)(sc + S_A + off) = *(uint32_t*)&h;
                *(uint32_t*)(sc + S_A + off + AL_OFF) = *(uint32_t*)&lo;
            }
            __syncthreads();
        }

        // -------- hidden layers --------
        #pragma unroll 1
        for (int l = 0; l < NHID; l++) {
            const __half* whg = g_Whi + (size_t)(e * 3 + l) * 65536;
            bias_s[tid] = __ldg(bh + (e * 3 + l) * 256 + tid);

            float cacc[2][8][4];
            #pragma unroll
            for (int mt = 0; mt < 2; mt++)
                #pragma unroll
                for (int nt = 0; nt < 8; nt++)
                    #pragma unroll
                    for (int q = 0; q < 4; q++) cacc[mt][nt][q] = 0.f;

            // cp.async: chunk = 256 rows x 16 k-halves (32B) = 8KB; 2x16B per thread
            // issue chunk 0
            {
                uint32_t db = smem0 + S_WB;
                const __half* sh = whg + tid * 256;
                CP16(db + w_sw(tid, 0), sh);
                CP16(db + w_sw(tid, 1), sh + 8);
                CP_COMMIT();
            }

            #pragma unroll 1
            for (int kc = 0; kc < 16; kc++) {
                const int buf = kc & 1;
                if (kc < 15) {
                    uint32_t db = smem0 + S_WB + ((kc + 1) & 1) * WBUF_SZ;
                    const __half* sh = whg + tid * 256 + (kc + 1) * 16;
                    CP16(db + w_sw(tid, 0), sh);
                    CP16(db + w_sw(tid, 1), sh + 8);
                    CP_COMMIT();
                    CP_WAIT1();
                } else {
                    CP_WAIT0();
                }
                __syncthreads();

                // A fragments for this k16 (hi + lo)
                uint32_t ahi[2][4], alo[2][4];
                #pragma unroll
                for (int mt = 0; mt < 2; mt++) {
                    uint32_t ml = (uint32_t)(m0l + mt * 16);
                    uint32_t u = (uint32_t)(kc * 2) + (lane >> 4);
                    uint32_t aa = smem0 + S_A + a_sw(ml, u);
                    LDSM4(ahi[mt][0], ahi[mt][1], ahi[mt][2], ahi[mt][3], aa);
                    LDSM4(alo[mt][0], alo[mt][1], alo[mt][2], alo[mt][3], aa + AL_OFF);
                }
                const uint32_t wb = smem0 + S_WB + buf * WBUF_SZ;

                // B fragments: software-pipelined double buffer; MMAs term-major
                uint32_t bf[2][4];
                LDSM4(bf[0][0], bf[0][1], bf[0][2], bf[0][3], wb + w_sw((uint32_t)bnl, bul));
                #pragma unroll
                for (int np = 0; np < 4; np++) {
                    const int cur = np & 1;
                    if (np < 3) {
                        uint32_t bo = wb + w_sw((uint32_t)(bnl + (np + 1) * 16), bul);
                        LDSM4(bf[cur ^ 1][0], bf[cur ^ 1][1], bf[cur ^ 1][2], bf[cur ^ 1][3], bo);
                    }
                    const uint32_t b0v = bf[cur][0], b1v = bf[cur][1];
                    const uint32_t b2v = bf[cur][2], b3v = bf[cur][3];
                    // term 1: A_hi * W  (4 independent accumulators)
                    mma16816(cacc[0][np * 2],     ahi[0], b0v, b1v);
                    mma16816(cacc[0][np * 2 + 1], ahi[0], b2v, b3v);
                    mma16816(cacc[1][np * 2],     ahi[1], b0v, b1v);
                    mma16816(cacc[1][np * 2 + 1], ahi[1], b2v, b3v);
                    // term 2: A_lo * W  (RAW distance 4 from term 1)
                    mma16816(cacc[0][np * 2],     alo[0], b0v, b1v);
                    mma16816(cacc[0][np * 2 + 1], alo[0], b2v, b3v);
                    mma16816(cacc[1][np * 2],     alo[1], b0v, b1v);
                    mma16816(cacc[1][np * 2 + 1], alo[1], b2v, b3v);
                }
                __syncthreads();
            }

            if (l < NHID - 1) {
                // bias + sin + fp16 split -> A bufs for next layer
                #pragma unroll
                for (int mt = 0; mt < 2; mt++) {
                    int r0 = warp_m * 32 + mt * 16 + (lane >> 2);
                    #pragma unroll
                    for (int nt = 0; nt < 8; nt++) {
                        int n0 = warp_n * 64 + nt * 8 + 2 * (lane & 3);
                        uint32_t u = (uint32_t)(warp_n * 8 + nt);
                        float2 bb = *(const float2*)(bias_s + n0);
                        float* cc = cacc[mt][nt];
                        float s00 = fast_sin(OMEGA * (cc[0] + bb.x));
                        float s01 = fast_sin(OMEGA * (cc[1] + bb.y));
                        float s10 = fast_sin(OMEGA * (cc[2] + bb.x));
                        float s11 = fast_sin(OMEGA * (cc[3] + bb.y));
                        __half2 h0 = __floats2half2_rn(s00, s01);
                        __half2 h1 = __floats2half2_rn(s10, s11);
                        __half2 l0 = __floats2half2_rn(s00 - __low2float(h0), s01 - __high2float(h0));
                        __half2 l1 = __floats2half2_rn(s10 - __low2float(h1), s11 - __high2float(h1));
                        uint32_t o0 = a_sw((uint32_t)r0, u) + (lane & 3) * 4;
                        uint32_t o1 = a_sw((uint32_t)(r0 + 8), u) + (lane & 3) * 4;
                        *(uint32_t*)(sc + S_A + o0) = *(uint32_t*)&h0;
                        *(uint32_t*)(sc + S_A + o1) = *(uint32_t*)&h1;
                        *(uint32_t*)(sc + S_A + o0 + AL_OFF) = *(uint32_t*)&l0;
                        *(uint32_t*)(sc + S_A + o1 + AL_OFF) = *(uint32_t*)&l1;
                    }
                }
                __syncthreads();
            } else {
                // last layer: bias + sin + Wout dot + reduce + gated combine
                float o[4][3];
                #pragma unroll
                for (int i = 0; i < 4; i++)
                    #pragma unroll
                    for (int c3 = 0; c3 < 3; c3++) o[i][c3] = 0.f;
                #pragma unroll
                for (int mt = 0; mt < 2; mt++) {
                    #pragma unroll
                    for (int nt = 0; nt < 8; nt++) {
                        int n0 = warp_n * 64 + nt * 8 + 2 * (lane & 3);
                        float2 bb = *(const float2*)(bias_s + n0);
                        float* cc = cacc[mt][nt];
                        float s00 = fast_sin(OMEGA * (cc[0] + bb.x));
                        float s01 = fast_sin(OMEGA * (cc[1] + bb.y));
                        float s10 = fast_sin(OMEGA * (cc[2] + bb.x));
                        float s11 = fast_sin(OMEGA * (cc[3] + bb.y));
                        const float* wA = wout_s + n0 * 4;
                        const float* wB = wout_s + (n0 + 1) * 4;
                        #pragma unroll
                        for (int c3 = 0; c3 < 3; c3++) {
                            o[mt * 2 + 0][c3] = fmaf(s00, wA[c3], fmaf(s01, wB[c3], o[mt * 2 + 0][c3]));
                            o[mt * 2 + 1][c3] = fmaf(s10, wA[c3], fmaf(s11, wB[c3], o[mt * 2 + 1][c3]));
                        }
                    }
                }
                #pragma unroll
                for (int i = 0; i < 4; i++)
                    #pragma unroll
                    for (int c3 = 0; c3 < 3; c3++) {
                        float v = o[i][c3];
                        v += __shfl_xor_sync(0xFFFFFFFF, v, 1);
                        v += __shfl_xor_sync(0xFFFFFFFF, v, 2);
                        o[i][c3] = v;
                    }
                __syncthreads();   // A reads done before red (alias) writes
                if ((lane & 3) == 0) {
                    int q = lane >> 2;
                    #pragma unroll
                    for (int i = 0; i < 4; i++) {
                        int r = warp_m * 32 + (i >> 1) * 16 + (i & 1) * 8 + q;
                        #pragma unroll
                        for (int c3 = 0; c3 < 3; c3++)
                            red[r * 12 + warp_n * 3 + c3] = o[i][c3];
                    }
                }
                __syncthreads();
                if (tid < TILE_M) {
                    float g = gts[e];
                    float oc0 = __ldg(bout + e * 3 + 0)
                              + red[tid * 12 + 0] + red[tid * 12 + 3] + red[tid * 12 + 6] + red[tid * 12 + 9];
                    float oc1 = __ldg(bout + e * 3 + 1)
                              + red[tid * 12 + 1] + red[tid * 12 + 4] + red[tid * 12 + 7] + red[tid * 12 + 10];
                    float oc2 = __ldg(bout + e * 3 + 2)
                              + red[tid * 12 + 2] + red[tid * 12 + 5] + red[tid * 12 + 8] + red[tid * 12 + 11];
                    cb0 = fmaf(g, oc0, cb0);
                    cb1 = fmaf(g, oc1, cb1);
                    cb2 = fmaf(g, oc2, cb2);
                }
                __syncthreads();   // red consumed before next expert's layer 0
            }
        }
    }

    if (tid < TILE_M) {
        int r = blockIdx.x * TILE_M + tid;
        out[r * 3 + 0] = cb0;
        out[r * 3 + 1] = cb1;
        out[r * 3 + 2] = cb2;
    }
}

extern "C" void kernel_launch(void* const* d_in, const int* in_sizes, int n_in,
                              void* d_out, int out_size) {
    (void)in_sizes; (void)n_in; (void)out_size;
    const float* x      = (const float*)d_in[0];
    const float* gate_W = (const float*)d_in[1];
    const float* gate_b = (const float*)d_in[2];
    const float* W0     = (const float*)d_in[3];
    const float* b0     = (const float*)d_in[4];
    const float* Wh     = (const float*)d_in[5];
    const float* bh     = (const float*)d_in[6];
    const float* Wout   = (const float*)d_in[7];
    const float* bout   = (const float*)d_in[8];
    float* out = (float*)d_out;

    dim3 pg(8, 8, NMAT), pb(32, 8);
    prep_split_kernel<<<pg, pb>>>(Wh);

    cudaFuncSetAttribute(moe_mma_kernel,
                         cudaFuncAttributeMaxDynamicSharedMemorySize, SMEM_BYTES);
    moe_mma_kernel<<<NPTS / TILE_M, NTHR, SMEM_BYTES>>>(
        x, gate_W, gate_b, W0, b0, Wh, bh, Wout, bout, out);
}

// round 6
// speedup vs baseline: 2.9561x; 1.1919x over previous
#include <cuda_runtime.h>
#include <cuda_fp16.h>
#include <cstdint>

#define E_EXP 8
#define H_DIM 256
#define NHID  3
#define OMEGA 30.0f
#define NPTS  65536
#define TILE_M 64
#define NTHR  256
#define NMAT  (E_EXP * NHID)

// ---- SMEM layout (bytes) ----
#define S_A     0              // A_hi: 64 rows x 512B (XOR swizzled)
#define AL_OFF  32768          // A_lo
#define S_WB    65536          // 8 warps x 4KB (2 bufs x 2KB each)
#define S_WOUT  98304          // 256*4 floats
#define S_BIAS  102400         // 256 floats
#define S_XS    103424         // pad to 1KB
#define SMEM_BYTES 104448      // 102KB -> 2 CTAs/SM
// aliases: red (64*24 floats = 6KB) over S_A; w0s (768 floats) over S_WB

// Pre-transposed fp16 weights: [mat][n_out][k_in]
__device__ __half g_Whi[NMAT * H_DIM * H_DIM];

static __device__ __forceinline__ uint32_t smem_u32(const void* p) {
    uint32_t a;
    asm("{ .reg .u64 t; cvta.to.shared.u64 t, %1; cvt.u32.u64 %0, t; }" : "=r"(a) : "l"(p));
    return a;
}

// A swizzle: row m (0..63) x 32 16B-units; unit low-3 bits XOR row low-3 bits
static __device__ __forceinline__ uint32_t a_sw(uint32_t m, uint32_t u) {
    return m * 512u + ((((u ^ m) & 7u) | (u & 24u)) << 4);
}
// per-warp W chunk: 32 rows x 64B (4 units); slot = (u ^ (n>>1)) & 3
static __device__ __forceinline__ uint32_t w_sw2(uint32_t n, uint32_t u) {
    return n * 64u + (((u ^ (n >> 1)) & 3u) << 4);
}

#define LDSM4(r0, r1, r2, r3, addr) \
    asm volatile("ldmatrix.sync.aligned.m8n8.x4.shared.b16 {%0,%1,%2,%3}, [%4];" \
                 : "=r"(r0), "=r"(r1), "=r"(r2), "=r"(r3) : "r"(addr))

static __device__ __forceinline__ void mma16816(float* c, const uint32_t* a,
                                                uint32_t b0, uint32_t b1) {
    asm volatile("mma.sync.aligned.m16n8k16.row.col.f32.f16.f16.f32 "
                 "{%0,%1,%2,%3}, {%4,%5,%6,%7}, {%8,%9}, {%0,%1,%2,%3};"
                 : "+f"(c[0]), "+f"(c[1]), "+f"(c[2]), "+f"(c[3])
                 : "r"(a[0]), "r"(a[1]), "r"(a[2]), "r"(a[3]), "r"(b0), "r"(b1));
}

#define CP16(dst, src) \
    asm volatile("cp.async.cg.shared.global [%0], [%1], 16;" :: "r"(dst), "l"(src))
#define CP_COMMIT() asm volatile("cp.async.commit_group;")
#define CP_WAIT0()  asm volatile("cp.async.wait_group 0;")
#define CP_WAIT1()  asm volatile("cp.async.wait_group 1;")

// fast sin, all FFMA
static __device__ __forceinline__ float fast_sin(float a) {
    float j = rintf(a * 0.63661977236758134308f);
    int q = (int)j;
    float r = fmaf(j, -1.57079637050628662109375f, a);
    r = fmaf(j, 4.37113883e-8f, r);
    float z = r * r;
    float sp = fmaf(z, -1.95152959e-4f, 8.33216087e-3f);
    sp = fmaf(z, sp, -1.66666546e-1f);
    sp = fmaf(sp * z, r, r);
    float cp = fmaf(z, 2.44331571e-5f, -1.38873163e-3f);
    cp = fmaf(z, cp, 4.16666418e-2f);
    cp = fmaf(z, cp, -5.0e-1f);
    cp = fmaf(z, cp, 1.0f);
    float res = (q & 1) ? cp : sp;
    return (q & 2) ? -res : res;
}

// ---------------- prep: transpose to [n][k] fp16 ----------------
__global__ void prep_split_kernel(const float* __restrict__ Wh) {
    __shared__ float t[32][33];
    const int mat = blockIdx.z;
    const float* src = Wh + (size_t)mat * 65536;     // [k][n]
    const int n0 = blockIdx.x * 32, k0 = blockIdx.y * 32;
    const int tx = threadIdx.x, ty = threadIdx.y;
    #pragma unroll
    for (int i = 0; i < 32; i += 8)
        t[ty + i][tx] = src[(size_t)(k0 + ty + i) * 256 + (n0 + tx)];
    __syncthreads();
    #pragma unroll
    for (int i = 0; i < 32; i += 8) {
        float w = t[tx][ty + i];
        size_t o = (size_t)mat * 65536 + (size_t)(n0 + ty + i) * 256 + (k0 + tx);
        g_Whi[o] = __float2half_rn(w);
    }
}

// ---------------- main kernel ----------------
extern __shared__ char smem[];

__global__ void __launch_bounds__(NTHR, 2)
moe_mma_kernel(const float* __restrict__ x,
               const float* __restrict__ gate_W,
               const float* __restrict__ gate_b,
               const float* __restrict__ W0,
               const float* __restrict__ b0,
               const float* __restrict__ Wh_unused,
               const float* __restrict__ bh,
               const float* __restrict__ Wout,
               const float* __restrict__ bout,
               float* __restrict__ out)
{
    const uint32_t smem0 = smem_u32(smem);
    char*  sc     = smem;
    float* wout_s = (float*)(sc + S_WOUT);
    float* bias_s = (float*)(sc + S_BIAS);
    float* xs     = (float*)(sc + S_XS);
    float* red    = (float*)(sc + S_A);      // alias (A dead then)
    float* w0s    = (float*)(sc + S_WB);     // alias (W bufs dead then)

    const int tid  = threadIdx.x;
    const int lane = tid & 31;
    const int wid  = tid >> 5;               // warp owns n-slice [wid*32, wid*32+32)
    const int nw   = wid * 32;

    const int m0l  = lane & 15;                              // A ldmatrix row base
    const int lrow = (lane & 7) + ((lane >> 4) & 1) * 8;     // B local row base
    const uint32_t uu = (lane >> 3) & 1;                     // B k-unit bit
    const uint32_t wbase = smem0 + S_WB + (uint32_t)wid * 4096u;

    if (tid < 128) xs[tid] = x[blockIdx.x * 128 + tid];
    __syncthreads();

    // gate softmax (threads < 64 own one point)
    float gts[E_EXP];
    float cb0 = 0.f, cb1 = 0.f, cb2 = 0.f;
    if (tid < TILE_M) {
        float x0 = xs[tid * 2], x1 = xs[tid * 2 + 1];
        float mx = -1e30f;
        #pragma unroll
        for (int e = 0; e < E_EXP; e++) {
            float v = fmaf(x0, __ldg(gate_W + e), fmaf(x1, __ldg(gate_W + 8 + e), __ldg(gate_b + e)));
            gts[e] = v; mx = fmaxf(mx, v);
        }
        float s = 0.f;
        #pragma unroll
        for (int e = 0; e < E_EXP; e++) { gts[e] = expf(gts[e] - mx); s += gts[e]; }
        float inv = 1.0f / s;
        #pragma unroll
        for (int e = 0; e < E_EXP; e++) gts[e] *= inv;
    }

    #pragma unroll 1
    for (int e = 0; e < E_EXP; e++) {
        // stage Wout[e] -> [256][4]; W0/b0 -> w0s[768] (aliases W bufs)
        wout_s[tid * 4 + 0] = __ldg(Wout + e * 768 + tid * 3 + 0);
        wout_s[tid * 4 + 1] = __ldg(Wout + e * 768 + tid * 3 + 1);
        wout_s[tid * 4 + 2] = __ldg(Wout + e * 768 + tid * 3 + 2);
        wout_s[tid * 4 + 3] = 0.f;
        for (int i = tid; i < 768; i += NTHR)
            w0s[i] = (i < 512) ? __ldg(W0 + e * 512 + i) : __ldg(b0 + e * 256 + (i - 512));
        __syncthreads();

        // -------- layer 0 (K=2, fp32) -> A hi/lo in SMEM --------
        {
            const int m = tid >> 2, p = tid & 3;
            const float x0 = xs[m * 2], x1 = xs[m * 2 + 1];
            #pragma unroll 4
            for (int j = 0; j < 32; j++) {
                int c0 = j * 8 + p * 2;
                float z0 = fmaf(x0, w0s[c0],     fmaf(x1, w0s[256 + c0],     w0s[512 + c0]));
                float z1 = fmaf(x0, w0s[c0 + 1], fmaf(x1, w0s[256 + c0 + 1], w0s[512 + c0 + 1]));
                float s0 = fast_sin(OMEGA * z0);
                float s1 = fast_sin(OMEGA * z1);
                __half2 h = __floats2half2_rn(s0, s1);
                __half2 lo = __floats2half2_rn(s0 - __low2float(h), s1 - __high2float(h));
                uint32_t off = a_sw(m, j) + p * 4;
                *(uint32_t*)(sc + S_A + off) = *(uint32_t*)&h;
                *(uint32_t*)(sc + S_A + off + AL_OFF) = *(uint32_t*)&lo;
            }
            __syncthreads();
        }

        // -------- hidden layers --------
        #pragma unroll 1
        for (int l = 0; l < NHID; l++) {
            const __half* whg = g_Whi + (size_t)(e * 3 + l) * 65536;
            bias_s[tid] = __ldg(bh + (e * 3 + l) * 256 + tid);

            float cacc[4][4][4];
            #pragma unroll
            for (int mt = 0; mt < 4; mt++)
                #pragma unroll
                for (int nt = 0; nt < 4; nt++)
                    #pragma unroll
                    for (int q = 0; q < 4; q++) cacc[mt][nt][q] = 0.f;

            // -------- per-warp barrier-free K-loop over 8 chunks of K=32 --------
            const __half* wsrc = whg + (size_t)(nw + lane) * 256;  // this lane's W row
            // prologue: chunks 0, 1
            #pragma unroll
            for (int j = 0; j < 2; j++) {
                uint32_t db = wbase + (uint32_t)j * 2048u;
                const __half* s = wsrc + j * 32;
                #pragma unroll
                for (int u = 0; u < 4; u++)
                    CP16(db + w_sw2((uint32_t)lane, (uint32_t)u), s + u * 8);
                CP_COMMIT();
            }

            #pragma unroll 1
            for (int c = 0; c < 8; c++) {
                if (c < 7) { CP_WAIT1(); } else { CP_WAIT0(); }
                __syncwarp();
                const uint32_t wb = wbase + (uint32_t)(c & 1) * 2048u;

                // B fragments for whole k32 chunk (4 n8-tiles x 2 k16)
                uint32_t bq[16];
                LDSM4(bq[0], bq[1], bq[2], bq[3],     wb + w_sw2((uint32_t)lrow,        uu));
                LDSM4(bq[4], bq[5], bq[6], bq[7],     wb + w_sw2((uint32_t)(lrow + 16), uu));
                LDSM4(bq[8], bq[9], bq[10], bq[11],   wb + w_sw2((uint32_t)lrow,        2u + uu));
                LDSM4(bq[12], bq[13], bq[14], bq[15], wb + w_sw2((uint32_t)(lrow + 16), 2u + uu));

                // issue chunk c+2 (overlaps DMA with MMAs below)
                if (c < 6) {
                    int j = c + 2;
                    uint32_t db = wbase + (uint32_t)(j & 1) * 2048u;
                    const __half* s = wsrc + j * 32;
                    #pragma unroll
                    for (int u = 0; u < 4; u++)
                        CP16(db + w_sw2((uint32_t)lane, (uint32_t)u), s + u * 8);
                    CP_COMMIT();
                }

                #pragma unroll
                for (int h = 0; h < 2; h++) {
                    const uint32_t ubase = (uint32_t)(c * 4 + h * 2) + (uint32_t)(lane >> 4);
                    uint32_t af[4][4];
                    #pragma unroll
                    for (int mt = 0; mt < 4; mt++) {
                        uint32_t aa = smem0 + S_A + a_sw((uint32_t)(mt * 16 + m0l), ubase);
                        LDSM4(af[mt][0], af[mt][1], af[mt][2], af[mt][3], aa);
                    }
                    #pragma unroll
                    for (int mt = 0; mt < 4; mt++)
                        #pragma unroll
                        for (int nt = 0; nt < 4; nt++)
                            mma16816(cacc[mt][nt], af[mt], bq[h * 8 + nt * 2], bq[h * 8 + nt * 2 + 1]);
                    #pragma unroll
                    for (int mt = 0; mt < 4; mt++) {
                        uint32_t aa = smem0 + S_A + AL_OFF + a_sw((uint32_t)(mt * 16 + m0l), ubase);
                        LDSM4(af[mt][0], af[mt][1], af[mt][2], af[mt][3], aa);
                    }
                    #pragma unroll
                    for (int mt = 0; mt < 4; mt++)
                        #pragma unroll
                        for (int nt = 0; nt < 4; nt++)
                            mma16816(cacc[mt][nt], af[mt], bq[h * 8 + nt * 2], bq[h * 8 + nt * 2 + 1]);
                }
            }

            __syncthreads();   // all warps' A reads done; bias_s visible

            if (l < NHID - 1) {
                // bias + sin + fp16 split -> A bufs (warp writes its own 32 cols)
                #pragma unroll
                for (int mt = 0; mt < 4; mt++) {
                    int r0 = mt * 16 + (lane >> 2);
                    #pragma unroll
                    for (int nt = 0; nt < 4; nt++) {
                        int n0 = nw + nt * 8 + 2 * (lane & 3);
                        uint32_t u = (uint32_t)(n0 >> 3);
                        float2 bb = *(const float2*)(bias_s + n0);
                        float* cc = cacc[mt][nt];
                        float s00 = fast_sin(OMEGA * (cc[0] + bb.x));
                        float s01 = fast_sin(OMEGA * (cc[1] + bb.y));
                        float s10 = fast_sin(OMEGA * (cc[2] + bb.x));
                        float s11 = fast_sin(OMEGA * (cc[3] + bb.y));
                        __half2 h0 = __floats2half2_rn(s00, s01);
                        __half2 h1 = __floats2half2_rn(s10, s11);
                        __half2 l0 = __floats2half2_rn(s00 - __low2float(h0), s01 - __high2float(h0));
                        __half2 l1 = __floats2half2_rn(s10 - __low2float(h1), s11 - __high2float(h1));
                        uint32_t o0 = a_sw((uint32_t)r0, u) + (lane & 3) * 4;
                        uint32_t o1 = a_sw((uint32_t)(r0 + 8), u) + (lane & 3) * 4;
                        *(uint32_t*)(sc + S_A + o0) = *(uint32_t*)&h0;
                        *(uint32_t*)(sc + S_A + o1) = *(uint32_t*)&h1;
                        *(uint32_t*)(sc + S_A + o0 + AL_OFF) = *(uint32_t*)&l0;
                        *(uint32_t*)(sc + S_A + o1 + AL_OFF) = *(uint32_t*)&l1;
                    }
                }
                __syncthreads();
            } else {
                // last layer: bias + sin + Wout dot + reduce + gated combine
                float o[8][3];
                #pragma unroll
                for (int i = 0; i < 8; i++)
                    #pragma unroll
                    for (int c3 = 0; c3 < 3; c3++) o[i][c3] = 0.f;
                #pragma unroll
                for (int mt = 0; mt < 4; mt++) {
                    #pragma unroll
                    for (int nt = 0; nt < 4; nt++) {
                        int n0 = nw + nt * 8 + 2 * (lane & 3);
                        float2 bb = *(const float2*)(bias_s + n0);
                        float* cc = cacc[mt][nt];
                        float s00 = fast_sin(OMEGA * (cc[0] + bb.x));
                        float s01 = fast_sin(OMEGA * (cc[1] + bb.y));
                        float s10 = fast_sin(OMEGA * (cc[2] + bb.x));
                        float s11 = fast_sin(OMEGA * (cc[3] + bb.y));
                        const float* wA = wout_s + n0 * 4;
                        const float* wB = wout_s + (n0 + 1) * 4;
                        #pragma unroll
                        for (int c3 = 0; c3 < 3; c3++) {
                            o[mt * 2 + 0][c3] = fmaf(s00, wA[c3], fmaf(s01, wB[c3], o[mt * 2 + 0][c3]));
                            o[mt * 2 + 1][c3] = fmaf(s10, wA[c3], fmaf(s11, wB[c3], o[mt * 2 + 1][c3]));
                        }
                    }
                }
                #pragma unroll
                for (int i = 0; i < 8; i++)
                    #pragma unroll
                    for (int c3 = 0; c3 < 3; c3++) {
                        float v = o[i][c3];
                        v += __shfl_xor_sync(0xFFFFFFFF, v, 1);
                        v += __shfl_xor_sync(0xFFFFFFFF, v, 2);
                        o[i][c3] = v;
                    }
                if ((lane & 3) == 0) {
                    int q = lane >> 2;
                    #pragma unroll
                    for (int mt = 0; mt < 4; mt++)
                        #pragma unroll
                        for (int i = 0; i < 2; i++) {
                            int r = mt * 16 + i * 8 + q;
                            #pragma unroll
                            for (int c3 = 0; c3 < 3; c3++)
                                red[r * 24 + wid * 3 + c3] = o[mt * 2 + i][c3];
                        }
                }
                __syncthreads();
                if (tid < TILE_M) {
                    float g = gts[e];
                    #pragma unroll
                    for (int c3 = 0; c3 < 3; c3++) {
                        float oc = __ldg(bout + e * 3 + c3);
                        #pragma unroll
                        for (int w = 0; w < 8; w++)
                            oc += red[tid * 24 + w * 3 + c3];
                        if (c3 == 0) cb0 = fmaf(g, oc, cb0);
                        else if (c3 == 1) cb1 = fmaf(g, oc, cb1);
                        else cb2 = fmaf(g, oc, cb2);
                    }
                }
                __syncthreads();   // red consumed before next expert's layer 0
            }
        }
    }

    if (tid < TILE_M) {
        int r = blockIdx.x * TILE_M + tid;
        out[r * 3 + 0] = cb0;
        out[r * 3 + 1] = cb1;
        out[r * 3 + 2] = cb2;
    }
}

extern "C" void kernel_launch(void* const* d_in, const int* in_sizes, int n_in,
                              void* d_out, int out_size) {
    (void)in_sizes; (void)n_in; (void)out_size;
    const float* x      = (const float*)d_in[0];
    const float* gate_W = (const float*)d_in[1];
    const float* gate_b = (const float*)d_in[2];
    const float* W0     = (const float*)d_in[3];
    const float* b0     = (const float*)d_in[4];
    const float* Wh     = (const float*)d_in[5];
    const float* bh     = (const float*)d_in[6];
    const float* Wout   = (const float*)d_in[7];
    const float* bout   = (const float*)d_in[8];
    float* out = (float*)d_out;

    dim3 pg(8, 8, NMAT), pb(32, 8);
    prep_split_kernel<<<pg, pb>>>(Wh);

    cudaFuncSetAttribute(moe_mma_kernel,
                         cudaFuncAttributeMaxDynamicSharedMemorySize, SMEM_BYTES);
    moe_mma_kernel<<<NPTS / TILE_M, NTHR, SMEM_BYTES>>>(
        x, gate_W, gate_b, W0, b0, Wh, bh, Wout, bout, out);
}